// round 3
// baseline (speedup 1.0000x reference)
#include <cuda_runtime.h>

#define N_NODES 10000
#define N_EDGES 640000
#define D_FEAT  128

// ---------------- scratch (static device globals; no allocations) ----------------
__device__ __align__(256) float g_dinv[N_NODES];
__device__ __align__(256) int   g_count[N_NODES];
__device__ __align__(256) int   g_cur[N_NODES];
__device__ __align__(256) int   g_off[N_NODES + 1];
__device__ __align__(256) int   g_csr_src[N_EDGES];
__device__ __align__(256) float g_csr_w[N_EDGES];
__device__ __align__(256) float g_bufA[N_NODES * D_FEAT];
__device__ __align__(256) float g_bufB[N_NODES * D_FEAT];
__device__ int g_is64;

// ---------------- dtype detection for edge_index ----------------
// If the buffer holds int64 (values < 2^31), every odd 32-bit word is 0.
// If it holds int32 node indices, odd words are genuine indices (~all nonzero).
__global__ void k_detect(const int* __restrict__ ei32) {
    if (threadIdx.x == 0 && blockIdx.x == 0) {
        int any = 0;
        for (int i = 0; i < 1024; i++) any |= ei32[2 * i + 1];
        g_is64 = (any == 0) ? 1 : 0;
    }
}

__device__ __forceinline__ int load_ei(const void* ei, int idx) {
    if (g_is64) return (int)((const long long*)ei)[idx];
    return ((const int*)ei)[idx];
}

// ---------------- graph-structure kernels ----------------

__global__ void k_zero() {
    int i = blockIdx.x * blockDim.x + threadIdx.x;
    if (i < N_NODES) { g_count[i] = 0; g_cur[i] = 0; }
}

__global__ void k_hist(const void* __restrict__ ei) {
    int i = blockIdx.x * blockDim.x + threadIdx.x;
    if (i < N_EDGES) {
        int d = load_ei(ei, N_EDGES + i);   // row 1 = dst
        if ((unsigned)d < N_NODES) atomicAdd(&g_count[d], 1);
    }
}

__global__ void k_dinv() {
    int i = blockIdx.x * blockDim.x + threadIdx.x;
    if (i < N_NODES) {
        // +1 for the self-loop; always >= 1
        g_dinv[i] = rsqrtf((float)(g_count[i] + 1));
    }
}

// single-block exclusive scan of g_count -> g_off (10001 entries)
__global__ void k_scan() {
    __shared__ int part[1024];
    const int CH = 10;                      // 1024*10 >= 10000
    int t = threadIdx.x;
    int base = t * CH;
    int s = 0;
#pragma unroll
    for (int i = 0; i < CH; i++) {
        int idx = base + i;
        if (idx < N_NODES) s += g_count[idx];
    }
    part[t] = s;
    __syncthreads();
    for (int d = 1; d < 1024; d <<= 1) {
        int v = (t >= d) ? part[t - d] : 0;
        __syncthreads();
        part[t] += v;
        __syncthreads();
    }
    int run = (t == 0) ? 0 : part[t - 1];
#pragma unroll
    for (int i = 0; i < CH; i++) {
        int idx = base + i;
        if (idx < N_NODES) {
            g_off[idx] = run;
            run += g_count[idx];
        } else if (idx == N_NODES) {
            g_off[N_NODES] = run;
        }
    }
}

__global__ void k_scatter(const void* __restrict__ ei) {
    int i = blockIdx.x * blockDim.x + threadIdx.x;
    if (i < N_EDGES) {
        int s = load_ei(ei, i);
        int d = load_ei(ei, N_EDGES + i);
        if ((unsigned)d < N_NODES) {
            int p = g_off[d] + atomicAdd(&g_cur[d], 1);
            bool sv = (unsigned)s < N_NODES;
            g_csr_src[p] = sv ? s : 0;
            g_csr_w[p]   = sv ? (g_dinv[s] * g_dinv[d]) : 0.0f;
        }
    }
}

// ---------------- aggregation: one warp per destination node ----------------
// out[v] = dinv[v]^2 * in[v] + sum_{e:(s->v)} dinv[s]*dinv[v] * in[s]
// Input: fin_ext if non-null, else g_bufB. Output: always g_bufA.
// Lane covers 4 features via float4.
__global__ void k_agg(const float* __restrict__ fin_ext) {
    const float* __restrict__ fin = fin_ext ? fin_ext : (const float*)g_bufB;
    float* __restrict__ fout = g_bufA;

    int v    = (blockIdx.x * blockDim.x + threadIdx.x) >> 5;
    int lane = threadIdx.x & 31;
    if (v >= N_NODES) return;

    float dv = g_dinv[v];
    float4 xv = ((const float4*)(fin + (size_t)v * D_FEAT))[lane];
    float sl = dv * dv;
    float4 acc = make_float4(xv.x * sl, xv.y * sl, xv.z * sl, xv.w * sl);

    int j   = g_off[v];
    int end = g_off[v + 1];
    for (; j + 4 <= end; j += 4) {
        int   s0 = g_csr_src[j],     s1 = g_csr_src[j + 1];
        int   s2 = g_csr_src[j + 2], s3 = g_csr_src[j + 3];
        float w0 = g_csr_w[j],       w1 = g_csr_w[j + 1];
        float w2 = g_csr_w[j + 2],   w3 = g_csr_w[j + 3];
        float4 f0 = ((const float4*)(fin + (size_t)s0 * D_FEAT))[lane];
        float4 f1 = ((const float4*)(fin + (size_t)s1 * D_FEAT))[lane];
        float4 f2 = ((const float4*)(fin + (size_t)s2 * D_FEAT))[lane];
        float4 f3 = ((const float4*)(fin + (size_t)s3 * D_FEAT))[lane];
        acc.x += w0 * f0.x; acc.y += w0 * f0.y; acc.z += w0 * f0.z; acc.w += w0 * f0.w;
        acc.x += w1 * f1.x; acc.y += w1 * f1.y; acc.z += w1 * f1.z; acc.w += w1 * f1.w;
        acc.x += w2 * f2.x; acc.y += w2 * f2.y; acc.z += w2 * f2.z; acc.w += w2 * f2.w;
        acc.x += w3 * f3.x; acc.y += w3 * f3.y; acc.z += w3 * f3.z; acc.w += w3 * f3.w;
    }
    for (; j < end; j++) {
        int   s = g_csr_src[j];
        float w = g_csr_w[j];
        float4 f = ((const float4*)(fin + (size_t)s * D_FEAT))[lane];
        acc.x += w * f.x; acc.y += w * f.y; acc.z += w * f.z; acc.w += w * f.w;
    }
    ((float4*)(fout + (size_t)v * D_FEAT))[lane] = acc;
}

// ---------------- GEMM: C[M,BN] = A[M,128] @ B[128,BN] + bias (+relu) ----------------
// SRC: 0 -> A = g_bufA, C = g_bufB;  1 -> A = g_bufB, C = Cext
template <int BN, bool RELU, int SRC>
__global__ void k_gemm(const float* __restrict__ B,
                       const float* __restrict__ bias,
                       float* __restrict__ Cext, int M) {
    const float* __restrict__ A = (SRC == 0) ? (const float*)g_bufA : (const float*)g_bufB;
    float* __restrict__ C = (SRC == 0) ? g_bufB : Cext;

    constexpr int BM = 64, BK = 16, TM = 4, TN = BN / 16;
    __shared__ __align__(16) float As[BK][BM];
    __shared__ __align__(16) float Bs[BK][BN];

    int t  = threadIdx.x;            // 0..255
    int tx = t & 15;                 // col group
    int ty = t >> 4;                 // row group
    int m0 = blockIdx.x * BM;

    float acc[TM][TN];
#pragma unroll
    for (int i = 0; i < TM; i++)
#pragma unroll
        for (int j = 0; j < TN; j++) acc[i][j] = 0.0f;

    for (int k0 = 0; k0 < 128; k0 += BK) {
        // A tile: 64x16, one float4 per thread, stored k-major in shared
        {
            int r  = t >> 2;             // 0..63
            int c  = (t & 3) * 4;        // 0,4,8,12
            int gm = m0 + r;
            float4 v = make_float4(0.f, 0.f, 0.f, 0.f);
            if (gm < M) v = *(const float4*)(A + (size_t)gm * 128 + k0 + c);
            As[c + 0][r] = v.x; As[c + 1][r] = v.y;
            As[c + 2][r] = v.z; As[c + 3][r] = v.w;
        }
        // B tile: 16xBN
        {
            constexpr int F4 = BK * BN / 4;
#pragma unroll
            for (int i = 0; i < F4 / 256; i++) {
                int idx = t + i * 256;
                int rr  = idx / (BN / 4);
                int cc  = (idx % (BN / 4)) * 4;
                *(float4*)&Bs[rr][cc] = *(const float4*)(B + (size_t)(k0 + rr) * BN + cc);
            }
        }
        __syncthreads();
#pragma unroll
        for (int kk = 0; kk < BK; kk++) {
            float a[TM], b[TN];
#pragma unroll
            for (int i = 0; i < TM; i++) a[i] = As[kk][ty * TM + i];
#pragma unroll
            for (int j = 0; j < TN; j++) b[j] = Bs[kk][tx * TN + j];
#pragma unroll
            for (int i = 0; i < TM; i++)
#pragma unroll
                for (int j = 0; j < TN; j++) acc[i][j] += a[i] * b[j];
        }
        __syncthreads();
    }

#pragma unroll
    for (int i = 0; i < TM; i++) {
        int gm = m0 + ty * TM + i;
        if (gm >= M) continue;
#pragma unroll
        for (int j = 0; j < TN; j += 4) {
            int col = tx * TN + j;
            float4 o;
            o.x = acc[i][j + 0] + bias[col + 0];
            o.y = acc[i][j + 1] + bias[col + 1];
            o.z = acc[i][j + 2] + bias[col + 2];
            o.w = acc[i][j + 3] + bias[col + 3];
            if (RELU) {
                o.x = fmaxf(o.x, 0.f); o.y = fmaxf(o.y, 0.f);
                o.z = fmaxf(o.z, 0.f); o.w = fmaxf(o.w, 0.f);
            }
            *(float4*)(C + (size_t)gm * BN + col) = o;
        }
    }
}

// ---------------- launch ----------------
extern "C" void kernel_launch(void* const* d_in, const int* in_sizes, int n_in,
                              void* d_out, int out_size) {
    const float* x  = (const float*)d_in[0];
    const void*  ei = d_in[1];
    const float* w1 = (const float*)d_in[2];
    const float* b1 = (const float*)d_in[3];
    const float* w2 = (const float*)d_in[4];
    const float* b2 = (const float*)d_in[5];
    const float* w3 = (const float*)d_in[6];
    const float* b3 = (const float*)d_in[7];
    const float* wo = (const float*)d_in[8];
    const float* bo = (const float*)d_in[9];
    float* out = (float*)d_out;

    const int TB = 256;
    // graph structure (recomputed every call; deterministic work)
    k_detect <<<1, 32>>>((const int*)ei);
    k_zero   <<<(N_NODES + TB - 1) / TB, TB>>>();
    k_hist   <<<(N_EDGES + TB - 1) / TB, TB>>>(ei);
    k_dinv   <<<(N_NODES + TB - 1) / TB, TB>>>();
    k_scan   <<<1, 1024>>>();
    k_scatter<<<(N_EDGES + TB - 1) / TB, TB>>>(ei);

    const int AGG_BLOCKS  = (N_NODES * 32 + TB - 1) / TB;   // one warp per node
    const int GEMM_BLOCKS = (N_NODES + 63) / 64;

    // layer 1: bufA = agg(x); bufB = relu(bufA @ W1 + b1)
    k_agg<<<AGG_BLOCKS, TB>>>(x);
    k_gemm<128, true, 0><<<GEMM_BLOCKS, TB>>>(w1, b1, nullptr, N_NODES);
    // layer 2: bufA = agg(bufB); bufB = relu(bufA @ W2 + b2)
    k_agg<<<AGG_BLOCKS, TB>>>(nullptr);
    k_gemm<128, true, 0><<<GEMM_BLOCKS, TB>>>(w2, b2, nullptr, N_NODES);
    // layer 3
    k_agg<<<AGG_BLOCKS, TB>>>(nullptr);
    k_gemm<128, true, 0><<<GEMM_BLOCKS, TB>>>(w3, b3, nullptr, N_NODES);
    // final linear: out = bufB @ Wout + bout
    k_gemm<64, false, 1><<<GEMM_BLOCKS, TB>>>(wo, bo, out, N_NODES);
}